// round 2
// baseline (speedup 1.0000x reference)
#include <cuda_runtime.h>
#include <math.h>

#define BB  4
#define NN  1024
#define DM_ 512
#define HH  8
#define CC  3
#define DC_ 16
#define DK_ 64
#define XW  (CC*DC_)   // 48

// ---------------- scratch (device globals; no allocation allowed) ----------
__device__ float g_Q[(size_t)BB*HH*NN*DK_];
__device__ float g_K[(size_t)BB*HH*NN*DK_];
__device__ float g_V[(size_t)BB*HH*NN*DK_];
__device__ float g_AO[(size_t)BB*NN*DM_];
__device__ float g_bias[(size_t)BB*HH*NN*NN];   // worst case; uniform case uses h=0 slice only
__device__ float g_sq[(size_t)BB*NN*CC];
__device__ float g_alpha[HH*CC];
__device__ float g_gcoef[HH*CC];
__device__ int   g_uniform;

// ---------------- coef prep: g = 1/(2 sigma^2), head-uniformity flag -------
__global__ void prep_coef_kernel(const float* __restrict__ alpha,
                                 const float* __restrict__ lsig) {
    if (threadIdx.x == 0 && blockIdx.x == 0) {
        for (int i = 0; i < HH*CC; i++) {
            float s = expf(lsig[i]);
            if (s < 1e-4f) s = 1e-4f;
            g_gcoef[i] = 1.0f / (2.0f * s * s);
            g_alpha[i] = alpha[i];
        }
        int uni = 1;
        for (int h = 1; h < HH; h++)
            for (int c = 0; c < CC; c++)
                if (alpha[h*CC+c] != alpha[c] || lsig[h*CC+c] != lsig[c]) uni = 0;
        g_uniform = uni;
    }
}

// ---------------- per-(b,n,c) squared norms --------------------------------
__global__ void sq_kernel(const float* __restrict__ x) {
    int t = blockIdx.x * blockDim.x + threadIdx.x;
    if (t >= BB*NN*CC) return;
    int c = t % CC; int bn = t / CC;
    const float* p = x + (size_t)bn * XW + c * DC_;
    float s = 0.f;
#pragma unroll
    for (int d = 0; d < DC_; d++) s += p[d] * p[d];
    g_sq[t] = s;
}

// ---------------- generic 64x64 tiled GEMM: out = A @ W^T + bias -----------
// A: [4096,512] row-major; W: [512,512] row-major (out[m,o] = sum_k A[m,k]W[o,k])
// HEADED: scatter o -> (head,dk) into [B,H,N,DK]; else plain [m,o].
template<bool HEADED>
__global__ __launch_bounds__(256)
void gemm_kernel(const float* __restrict__ A, const float* __restrict__ W,
                 const float* __restrict__ bias, float* __restrict__ out,
                 float outScale) {
    __shared__ float As[64][17];
    __shared__ float Bs[64][17];
    const int tid = threadIdx.x;
    const int tx = tid & 15, ty = tid >> 4;
    const int m0 = blockIdx.y * 64, o0 = blockIdx.x * 64;
    const int lrow = tid >> 2, lk = (tid & 3) * 4;

    float acc[4][4] = {};

    for (int kb = 0; kb < 512; kb += 16) {
        __syncthreads();
        float4 av = *(const float4*)(A + (size_t)(m0 + lrow) * 512 + kb + lk);
        float4 wv = *(const float4*)(W + (size_t)(o0 + lrow) * 512 + kb + lk);
        As[lrow][lk+0] = av.x; As[lrow][lk+1] = av.y; As[lrow][lk+2] = av.z; As[lrow][lk+3] = av.w;
        Bs[lrow][lk+0] = wv.x; Bs[lrow][lk+1] = wv.y; Bs[lrow][lk+2] = wv.z; Bs[lrow][lk+3] = wv.w;
        __syncthreads();
#pragma unroll
        for (int kk = 0; kk < 16; kk++) {
            float a[4], b[4];
#pragma unroll
            for (int r = 0; r < 4; r++) a[r] = As[4*ty + r][kk];
#pragma unroll
            for (int c = 0; c < 4; c++) b[c] = Bs[4*tx + c][kk];
#pragma unroll
            for (int r = 0; r < 4; r++)
#pragma unroll
                for (int c = 0; c < 4; c++) acc[r][c] = fmaf(a[r], b[c], acc[r][c]);
        }
    }

#pragma unroll
    for (int r = 0; r < 4; r++) {
        int m = m0 + 4*ty + r;
#pragma unroll
        for (int c = 0; c < 4; c++) {
            int o = o0 + 4*tx + c;
            float v = (acc[r][c] + bias[o]) * outScale;
            if (HEADED) {
                int b2 = m >> 10, n2 = m & 1023;
                int hd = o >> 6, dk = o & 63;
                out[(((size_t)(b2*HH + hd)) * NN + n2) * DK_ + dk] = v;
            } else {
                out[(size_t)m * DM_ + o] = v;
            }
        }
    }
}

// ---------------- geodesic bias matrix -------------------------------------
// bias[b,h,i,j] = sum_c alpha[h,c] * exp(-max(|xi_c - xj_c|^2,0) * g[h,c])
// If coefficients are head-uniform, only h=0 is computed/stored.
__global__ __launch_bounds__(256)
void bias_kernel(const float* __restrict__ x) {
    __shared__ float Xi[64][49];
    __shared__ float Xj[64][49];
    __shared__ float sqi[64][3];
    __shared__ float sqj[64][3];

    const int bh = blockIdx.z;
    const int h2 = bh & (HH-1);
    const int b2 = bh >> 3;
    if (g_uniform && h2 > 0) return;

    const int i0 = blockIdx.y * 64, j0 = blockIdx.x * 64;
    const int tid = threadIdx.x;
    const int tx = tid & 15, ty = tid >> 4;

    const float* xb = x + (size_t)b2 * NN * XW;
#pragma unroll
    for (int t = 0; t < 12; t++) {
        int idx = tid + t * 256;
        int row = idx / XW, col = idx % XW;
        Xi[row][col] = xb[(size_t)(i0 + row) * XW + col];
        Xj[row][col] = xb[(size_t)(j0 + row) * XW + col];
    }
    if (tid < 192) {
        int row = tid / 3, c = tid % 3;
        sqi[row][c] = g_sq[((size_t)b2 * NN + i0 + row) * CC + c];
        sqj[row][c] = g_sq[((size_t)b2 * NN + j0 + row) * CC + c];
    }
    __syncthreads();

    float Acf[CC], Gcf[CC];
#pragma unroll
    for (int c = 0; c < CC; c++) { Acf[c] = g_alpha[h2*CC + c]; Gcf[c] = g_gcoef[h2*CC + c]; }

    float* outp = g_bias + (size_t)(b2*HH + h2) * NN * NN;

#pragma unroll
    for (int r = 0; r < 4; r++) {
        int i = 4*ty + r;
#pragma unroll
        for (int c = 0; c < 4; c++) {
            int j = 4*tx + c;
            float bsum = 0.f;
#pragma unroll
            for (int cm = 0; cm < CC; cm++) {
                float inner = 0.f;
#pragma unroll
                for (int d = 0; d < DC_; d++)
                    inner = fmaf(Xi[i][cm*DC_ + d], Xj[j][cm*DC_ + d], inner);
                float dd = sqi[i][cm] + sqj[j][cm] - 2.f * inner;
                dd = fmaxf(dd, 0.f);
                bsum = fmaf(Acf[cm], __expf(-dd * Gcf[cm]), bsum);
            }
            outp[(size_t)(i0 + i) * NN + (j0 + j)] = bsum;
        }
    }
}

// ---------------- fused flash-style attention ------------------------------
// Block: one (b,h) x 64 query rows. Online softmax over 16 tiles of 64 keys.
__global__ __launch_bounds__(256)
void attn_kernel() {
    extern __shared__ float sm[];
    float* Qs = sm;               // 64*65
    float* Ks = Qs + 64*65;
    float* Vs = Ks + 64*65;
    float* Ps = Vs + 64*65;

    const int bh = blockIdx.y;
    const int b2 = bh >> 3, h2 = bh & 7;
    const int i0 = blockIdx.x * 64;
    const int tid = threadIdx.x;
    const int tx = tid & 15, ty = tid >> 4;
    const int heff = g_uniform ? 0 : h2;

    const float* Qg = g_Q + ((size_t)bh * NN + i0) * DK_;
    const float* Kg = g_K + (size_t)bh * NN * DK_;
    const float* Vg = g_V + (size_t)bh * NN * DK_;
    const float* Bg = g_bias + ((size_t)(b2*HH + heff) * NN + i0) * NN;

#pragma unroll
    for (int t = 0; t < 4; t++) {
        int idx = tid + t * 256;
        int row = idx >> 4, c4 = (idx & 15) * 4;
        float4 v = *(const float4*)(Qg + (size_t)row * DK_ + c4);
        Qs[row*65 + c4 + 0] = v.x; Qs[row*65 + c4 + 1] = v.y;
        Qs[row*65 + c4 + 2] = v.z; Qs[row*65 + c4 + 3] = v.w;
    }

    float m_r[4], l_r[4], O[4][4] = {};
#pragma unroll
    for (int r = 0; r < 4; r++) { m_r[r] = -1e30f; l_r[r] = 0.f; }

    for (int jt = 0; jt < 16; jt++) {
        const int j0 = jt * 64;
        __syncthreads();
#pragma unroll
        for (int t = 0; t < 4; t++) {
            int idx = tid + t * 256;
            int row = idx >> 4, c4 = (idx & 15) * 4;
            float4 kv = *(const float4*)(Kg + (size_t)(j0 + row) * DK_ + c4);
            float4 vv = *(const float4*)(Vg + (size_t)(j0 + row) * DK_ + c4);
            Ks[row*65 + c4 + 0] = kv.x; Ks[row*65 + c4 + 1] = kv.y;
            Ks[row*65 + c4 + 2] = kv.z; Ks[row*65 + c4 + 3] = kv.w;
            Vs[row*65 + c4 + 0] = vv.x; Vs[row*65 + c4 + 1] = vv.y;
            Vs[row*65 + c4 + 2] = vv.z; Vs[row*65 + c4 + 3] = vv.w;
        }
        __syncthreads();

        // S = Q K^T  (Q pre-scaled by 1/sqrt(dk))
        float s[4][4] = {};
#pragma unroll 8
        for (int kk = 0; kk < 64; kk++) {
            float a[4], b[4];
#pragma unroll
            for (int r = 0; r < 4; r++) a[r] = Qs[(4*ty + r)*65 + kk];
#pragma unroll
            for (int c = 0; c < 4; c++) b[c] = Ks[(4*tx + c)*65 + kk];
#pragma unroll
            for (int r = 0; r < 4; r++)
#pragma unroll
                for (int c = 0; c < 4; c++) s[r][c] = fmaf(a[r], b[c], s[r][c]);
        }

        // + geodesic bias
#pragma unroll
        for (int r = 0; r < 4; r++) {
            float4 bv = *(const float4*)(Bg + (size_t)(4*ty + r) * NN + j0 + 4*tx);
            s[r][0] += bv.x; s[r][1] += bv.y; s[r][2] += bv.z; s[r][3] += bv.w;
        }

        // online softmax update
#pragma unroll
        for (int r = 0; r < 4; r++) {
            float mt = fmaxf(fmaxf(s[r][0], s[r][1]), fmaxf(s[r][2], s[r][3]));
#pragma unroll
            for (int off = 1; off < 16; off <<= 1)
                mt = fmaxf(mt, __shfl_xor_sync(0xffffffffu, mt, off));
            float mnew = fmaxf(m_r[r], mt);
            float fac = __expf(m_r[r] - mnew);
            float rs = 0.f;
#pragma unroll
            for (int c = 0; c < 4; c++) { s[r][c] = __expf(s[r][c] - mnew); rs += s[r][c]; }
#pragma unroll
            for (int off = 1; off < 16; off <<= 1)
                rs += __shfl_xor_sync(0xffffffffu, rs, off);
            l_r[r] = l_r[r] * fac + rs;
            m_r[r] = mnew;
#pragma unroll
            for (int c = 0; c < 4; c++) O[r][c] *= fac;
        }

        // stage P, then O += P @ V
#pragma unroll
        for (int r = 0; r < 4; r++)
#pragma unroll
            for (int c = 0; c < 4; c++)
                Ps[(4*ty + r)*65 + 4*tx + c] = s[r][c];
        __syncthreads();

#pragma unroll 8
        for (int j = 0; j < 64; j++) {
            float pr[4], vb[4];
#pragma unroll
            for (int r = 0; r < 4; r++) pr[r] = Ps[(4*ty + r)*65 + j];
#pragma unroll
            for (int c = 0; c < 4; c++) vb[c] = Vs[j*65 + 4*tx + c];
#pragma unroll
            for (int r = 0; r < 4; r++)
#pragma unroll
                for (int c = 0; c < 4; c++) O[r][c] = fmaf(pr[r], vb[c], O[r][c]);
        }
    }

#pragma unroll
    for (int r = 0; r < 4; r++) {
        int n2 = i0 + 4*ty + r;
        float invl = 1.f / l_r[r];
#pragma unroll
        for (int c = 0; c < 4; c++)
            g_AO[((size_t)b2 * NN + n2) * DM_ + h2*DK_ + 4*tx + c] = O[r][c] * invl;
    }
}

// ---------------- launcher -------------------------------------------------
extern "C" void kernel_launch(void* const* d_in, const int* in_sizes, int n_in,
                              void* d_out, int out_size) {
    const float* h    = (const float*)d_in[0];
    const float* x    = (const float*)d_in[1];
    const float* Wq   = (const float*)d_in[2];
    const float* bq   = (const float*)d_in[3];
    const float* Wk   = (const float*)d_in[4];
    const float* bk   = (const float*)d_in[5];
    const float* Wv   = (const float*)d_in[6];
    const float* bv   = (const float*)d_in[7];
    const float* Wo   = (const float*)d_in[8];
    const float* bo   = (const float*)d_in[9];
    const float* alpha= (const float*)d_in[10];
    const float* lsig = (const float*)d_in[11];
    float* out = (float*)d_out;

    void *pQ, *pK, *pV, *pAO;
    cudaGetSymbolAddress(&pQ,  g_Q);
    cudaGetSymbolAddress(&pK,  g_K);
    cudaGetSymbolAddress(&pV,  g_V);
    cudaGetSymbolAddress(&pAO, g_AO);

    prep_coef_kernel<<<1, 32>>>(alpha, lsig);
    sq_kernel<<<(BB*NN*CC + 127)/128, 128>>>(x);

    dim3 ggrid(DM_/64, (BB*NN)/64);   // (8, 64)
    gemm_kernel<true><<<ggrid, 256>>>(h, Wq, bq, (float*)pQ, 0.125f);
    gemm_kernel<true><<<ggrid, 256>>>(h, Wk, bk, (float*)pK, 1.0f);
    gemm_kernel<true><<<ggrid, 256>>>(h, Wv, bv, (float*)pV, 1.0f);

    bias_kernel<<<dim3(NN/64, NN/64, BB*HH), 256>>>(x);

    const int SMEM = 4 * 64 * 65 * sizeof(float);  // 66560 B
    cudaFuncSetAttribute(attn_kernel, cudaFuncAttributeMaxDynamicSharedMemorySize, SMEM);
    attn_kernel<<<dim3(NN/64, BB*HH), 256, SMEM>>>();

    gemm_kernel<false><<<ggrid, 256>>>((const float*)pAO, Wo, bo, out, 1.0f);
}

// round 3
// speedup vs baseline: 1.0016x; 1.0016x over previous
#include <cuda_runtime.h>
#include <math.h>

#define BB  4
#define NN  1024
#define DM_ 512
#define HH  8
#define CC  3
#define DC_ 16
#define DK_ 64
#define XW  (CC*DC_)   // 48

// ---------------- scratch (device globals; no allocation allowed) ----------
__device__ float g_Q[(size_t)BB*HH*NN*DK_];
__device__ float g_K[(size_t)BB*HH*NN*DK_];
__device__ float g_V[(size_t)BB*HH*NN*DK_];
__device__ float g_AO[(size_t)BB*NN*DM_];
__device__ float g_bias[(size_t)BB*HH*NN*NN];   // worst case; uniform case uses h=0 slice only
__device__ float g_sq[(size_t)BB*NN*CC];
__device__ float g_alpha[HH*CC];
__device__ float g_gcoef[HH*CC];
__device__ int   g_uniform;

// ---------------- coef prep: g = 1/(2 sigma^2), head-uniformity flag -------
__global__ void prep_coef_kernel(const float* __restrict__ alpha,
                                 const float* __restrict__ lsig) {
    if (threadIdx.x == 0 && blockIdx.x == 0) {
        for (int i = 0; i < HH*CC; i++) {
            float s = expf(lsig[i]);
            if (s < 1e-4f) s = 1e-4f;
            g_gcoef[i] = 1.0f / (2.0f * s * s);
            g_alpha[i] = alpha[i];
        }
        int uni = 1;
        for (int h = 1; h < HH; h++)
            for (int c = 0; c < CC; c++)
                if (alpha[h*CC+c] != alpha[c] || lsig[h*CC+c] != lsig[c]) uni = 0;
        g_uniform = uni;
    }
}

// ---------------- per-(b,n,c) squared norms --------------------------------
__global__ void sq_kernel(const float* __restrict__ x) {
    int t = blockIdx.x * blockDim.x + threadIdx.x;
    if (t >= BB*NN*CC) return;
    int c = t % CC; int bn = t / CC;
    const float* p = x + (size_t)bn * XW + c * DC_;
    float s = 0.f;
#pragma unroll
    for (int d = 0; d < DC_; d++) s += p[d] * p[d];
    g_sq[t] = s;
}

// ---------------- generic 64x64 tiled GEMM: out = A @ W^T + bias -----------
// A: [4096,512] row-major; W: [512,512] row-major (out[m,o] = sum_k A[m,k]W[o,k])
// HEADED: scatter o -> (head,dk) into [B,H,N,DK]; else plain [m,o].
template<bool HEADED>
__global__ __launch_bounds__(256)
void gemm_kernel(const float* __restrict__ A, const float* __restrict__ W,
                 const float* __restrict__ bias, float* __restrict__ out,
                 float outScale) {
    __shared__ float As[64][17];
    __shared__ float Bs[64][17];
    const int tid = threadIdx.x;
    const int tx = tid & 15, ty = tid >> 4;
    const int m0 = blockIdx.y * 64, o0 = blockIdx.x * 64;
    const int lrow = tid >> 2, lk = (tid & 3) * 4;

    float acc[4][4] = {};

    for (int kb = 0; kb < 512; kb += 16) {
        __syncthreads();
        float4 av = *(const float4*)(A + (size_t)(m0 + lrow) * 512 + kb + lk);
        float4 wv = *(const float4*)(W + (size_t)(o0 + lrow) * 512 + kb + lk);
        As[lrow][lk+0] = av.x; As[lrow][lk+1] = av.y; As[lrow][lk+2] = av.z; As[lrow][lk+3] = av.w;
        Bs[lrow][lk+0] = wv.x; Bs[lrow][lk+1] = wv.y; Bs[lrow][lk+2] = wv.z; Bs[lrow][lk+3] = wv.w;
        __syncthreads();
#pragma unroll
        for (int kk = 0; kk < 16; kk++) {
            float a[4], b[4];
#pragma unroll
            for (int r = 0; r < 4; r++) a[r] = As[4*ty + r][kk];
#pragma unroll
            for (int c = 0; c < 4; c++) b[c] = Bs[4*tx + c][kk];
#pragma unroll
            for (int r = 0; r < 4; r++)
#pragma unroll
                for (int c = 0; c < 4; c++) acc[r][c] = fmaf(a[r], b[c], acc[r][c]);
        }
    }

#pragma unroll
    for (int r = 0; r < 4; r++) {
        int m = m0 + 4*ty + r;
#pragma unroll
        for (int c = 0; c < 4; c++) {
            int o = o0 + 4*tx + c;
            float v = (acc[r][c] + bias[o]) * outScale;
            if (HEADED) {
                int b2 = m >> 10, n2 = m & 1023;
                int hd = o >> 6, dk = o & 63;
                out[(((size_t)(b2*HH + hd)) * NN + n2) * DK_ + dk] = v;
            } else {
                out[(size_t)m * DM_ + o] = v;
            }
        }
    }
}

// ---------------- geodesic bias matrix -------------------------------------
// bias[b,h,i,j] = sum_c alpha[h,c] * exp(-max(|xi_c - xj_c|^2,0) * g[h,c])
// If coefficients are head-uniform, only h=0 is computed/stored.
__global__ __launch_bounds__(256)
void bias_kernel(const float* __restrict__ x) {
    __shared__ float Xi[64][49];
    __shared__ float Xj[64][49];
    __shared__ float sqi[64][3];
    __shared__ float sqj[64][3];

    const int bh = blockIdx.z;
    const int h2 = bh & (HH-1);
    const int b2 = bh >> 3;
    if (g_uniform && h2 > 0) return;

    const int i0 = blockIdx.y * 64, j0 = blockIdx.x * 64;
    const int tid = threadIdx.x;
    const int tx = tid & 15, ty = tid >> 4;

    const float* xb = x + (size_t)b2 * NN * XW;
#pragma unroll
    for (int t = 0; t < 12; t++) {
        int idx = tid + t * 256;
        int row = idx / XW, col = idx % XW;
        Xi[row][col] = xb[(size_t)(i0 + row) * XW + col];
        Xj[row][col] = xb[(size_t)(j0 + row) * XW + col];
    }
    if (tid < 192) {
        int row = tid / 3, c = tid % 3;
        sqi[row][c] = g_sq[((size_t)b2 * NN + i0 + row) * CC + c];
        sqj[row][c] = g_sq[((size_t)b2 * NN + j0 + row) * CC + c];
    }
    __syncthreads();

    float Acf[CC], Gcf[CC];
#pragma unroll
    for (int c = 0; c < CC; c++) { Acf[c] = g_alpha[h2*CC + c]; Gcf[c] = g_gcoef[h2*CC + c]; }

    float* outp = g_bias + (size_t)(b2*HH + h2) * NN * NN;

#pragma unroll
    for (int r = 0; r < 4; r++) {
        int i = 4*ty + r;
#pragma unroll
        for (int c = 0; c < 4; c++) {
            int j = 4*tx + c;
            float bsum = 0.f;
#pragma unroll
            for (int cm = 0; cm < CC; cm++) {
                float inner = 0.f;
#pragma unroll
                for (int d = 0; d < DC_; d++)
                    inner = fmaf(Xi[i][cm*DC_ + d], Xj[j][cm*DC_ + d], inner);
                float dd = sqi[i][cm] + sqj[j][cm] - 2.f * inner;
                dd = fmaxf(dd, 0.f);
                bsum = fmaf(Acf[cm], __expf(-dd * Gcf[cm]), bsum);
            }
            outp[(size_t)(i0 + i) * NN + (j0 + j)] = bsum;
        }
    }
}

// ---------------- fused flash-style attention ------------------------------
// Block: one (b,h) x 64 query rows. Online softmax over 16 tiles of 64 keys.
__global__ __launch_bounds__(256)
void attn_kernel() {
    extern __shared__ float sm[];
    float* Qs = sm;               // 64*65
    float* Ks = Qs + 64*65;
    float* Vs = Ks + 64*65;
    float* Ps = Vs + 64*65;

    const int bh = blockIdx.y;
    const int b2 = bh >> 3, h2 = bh & 7;
    const int i0 = blockIdx.x * 64;
    const int tid = threadIdx.x;
    const int tx = tid & 15, ty = tid >> 4;
    const int heff = g_uniform ? 0 : h2;

    const float* Qg = g_Q + ((size_t)bh * NN + i0) * DK_;
    const float* Kg = g_K + (size_t)bh * NN * DK_;
    const float* Vg = g_V + (size_t)bh * NN * DK_;
    const float* Bg = g_bias + ((size_t)(b2*HH + heff) * NN + i0) * NN;

#pragma unroll
    for (int t = 0; t < 4; t++) {
        int idx = tid + t * 256;
        int row = idx >> 4, c4 = (idx & 15) * 4;
        float4 v = *(const float4*)(Qg + (size_t)row * DK_ + c4);
        Qs[row*65 + c4 + 0] = v.x; Qs[row*65 + c4 + 1] = v.y;
        Qs[row*65 + c4 + 2] = v.z; Qs[row*65 + c4 + 3] = v.w;
    }

    float m_r[4], l_r[4], O[4][4] = {};
#pragma unroll
    for (int r = 0; r < 4; r++) { m_r[r] = -1e30f; l_r[r] = 0.f; }

    for (int jt = 0; jt < 16; jt++) {
        const int j0 = jt * 64;
        __syncthreads();
#pragma unroll
        for (int t = 0; t < 4; t++) {
            int idx = tid + t * 256;
            int row = idx >> 4, c4 = (idx & 15) * 4;
            float4 kv = *(const float4*)(Kg + (size_t)(j0 + row) * DK_ + c4);
            float4 vv = *(const float4*)(Vg + (size_t)(j0 + row) * DK_ + c4);
            Ks[row*65 + c4 + 0] = kv.x; Ks[row*65 + c4 + 1] = kv.y;
            Ks[row*65 + c4 + 2] = kv.z; Ks[row*65 + c4 + 3] = kv.w;
            Vs[row*65 + c4 + 0] = vv.x; Vs[row*65 + c4 + 1] = vv.y;
            Vs[row*65 + c4 + 2] = vv.z; Vs[row*65 + c4 + 3] = vv.w;
        }
        __syncthreads();

        // S = Q K^T  (Q pre-scaled by 1/sqrt(dk))
        float s[4][4] = {};
#pragma unroll 8
        for (int kk = 0; kk < 64; kk++) {
            float a[4], b[4];
#pragma unroll
            for (int r = 0; r < 4; r++) a[r] = Qs[(4*ty + r)*65 + kk];
#pragma unroll
            for (int c = 0; c < 4; c++) b[c] = Ks[(4*tx + c)*65 + kk];
#pragma unroll
            for (int r = 0; r < 4; r++)
#pragma unroll
                for (int c = 0; c < 4; c++) s[r][c] = fmaf(a[r], b[c], s[r][c]);
        }

        // + geodesic bias
#pragma unroll
        for (int r = 0; r < 4; r++) {
            float4 bv = *(const float4*)(Bg + (size_t)(4*ty + r) * NN + j0 + 4*tx);
            s[r][0] += bv.x; s[r][1] += bv.y; s[r][2] += bv.z; s[r][3] += bv.w;
        }

        // online softmax update
#pragma unroll
        for (int r = 0; r < 4; r++) {
            float mt = fmaxf(fmaxf(s[r][0], s[r][1]), fmaxf(s[r][2], s[r][3]));
#pragma unroll
            for (int off = 1; off < 16; off <<= 1)
                mt = fmaxf(mt, __shfl_xor_sync(0xffffffffu, mt, off));
            float mnew = fmaxf(m_r[r], mt);
            float fac = __expf(m_r[r] - mnew);
            float rs = 0.f;
#pragma unroll
            for (int c = 0; c < 4; c++) { s[r][c] = __expf(s[r][c] - mnew); rs += s[r][c]; }
#pragma unroll
            for (int off = 1; off < 16; off <<= 1)
                rs += __shfl_xor_sync(0xffffffffu, rs, off);
            l_r[r] = l_r[r] * fac + rs;
            m_r[r] = mnew;
#pragma unroll
            for (int c = 0; c < 4; c++) O[r][c] *= fac;
        }

        // stage P, then O += P @ V
#pragma unroll
        for (int r = 0; r < 4; r++)
#pragma unroll
            for (int c = 0; c < 4; c++)
                Ps[(4*ty + r)*65 + 4*tx + c] = s[r][c];
        __syncthreads();

#pragma unroll 8
        for (int j = 0; j < 64; j++) {
            float pr[4], vb[4];
#pragma unroll
            for (int r = 0; r < 4; r++) pr[r] = Ps[(4*ty + r)*65 + j];
#pragma unroll
            for (int c = 0; c < 4; c++) vb[c] = Vs[j*65 + 4*tx + c];
#pragma unroll
            for (int r = 0; r < 4; r++)
#pragma unroll
                for (int c = 0; c < 4; c++) O[r][c] = fmaf(pr[r], vb[c], O[r][c]);
        }
    }

#pragma unroll
    for (int r = 0; r < 4; r++) {
        int n2 = i0 + 4*ty + r;
        float invl = 1.f / l_r[r];
#pragma unroll
        for (int c = 0; c < 4; c++)
            g_AO[((size_t)b2 * NN + n2) * DM_ + h2*DK_ + 4*tx + c] = O[r][c] * invl;
    }
}

// ---------------- launcher -------------------------------------------------
extern "C" void kernel_launch(void* const* d_in, const int* in_sizes, int n_in,
                              void* d_out, int out_size) {
    const float* h    = (const float*)d_in[0];
    const float* x    = (const float*)d_in[1];
    const float* Wq   = (const float*)d_in[2];
    const float* bq   = (const float*)d_in[3];
    const float* Wk   = (const float*)d_in[4];
    const float* bk   = (const float*)d_in[5];
    const float* Wv   = (const float*)d_in[6];
    const float* bv   = (const float*)d_in[7];
    const float* Wo   = (const float*)d_in[8];
    const float* bo   = (const float*)d_in[9];
    const float* alpha= (const float*)d_in[10];
    const float* lsig = (const float*)d_in[11];
    float* out = (float*)d_out;

    void *pQ, *pK, *pV, *pAO;
    cudaGetSymbolAddress(&pQ,  g_Q);
    cudaGetSymbolAddress(&pK,  g_K);
    cudaGetSymbolAddress(&pV,  g_V);
    cudaGetSymbolAddress(&pAO, g_AO);

    prep_coef_kernel<<<1, 32>>>(alpha, lsig);
    sq_kernel<<<(BB*NN*CC + 127)/128, 128>>>(x);

    dim3 ggrid(DM_/64, (BB*NN)/64);   // (8, 64)
    gemm_kernel<true><<<ggrid, 256>>>(h, Wq, bq, (float*)pQ, 0.125f);
    gemm_kernel<true><<<ggrid, 256>>>(h, Wk, bk, (float*)pK, 1.0f);
    gemm_kernel<true><<<ggrid, 256>>>(h, Wv, bv, (float*)pV, 1.0f);

    bias_kernel<<<dim3(NN/64, NN/64, BB*HH), 256>>>(x);

    const int SMEM = 4 * 64 * 65 * sizeof(float);  // 66560 B
    cudaFuncSetAttribute(attn_kernel, cudaFuncAttributeMaxDynamicSharedMemorySize, SMEM);
    attn_kernel<<<dim3(NN/64, BB*HH), 256, SMEM>>>();

    gemm_kernel<false><<<ggrid, 256>>>((const float*)pAO, Wo, bo, out, 1.0f);
}